// round 9
// baseline (speedup 1.0000x reference)
#include <cuda_runtime.h>
#include <cstdint>
#include <cstddef>

// ---------------- problem constants ----------------
#define Q_ROWS  4096
#define N_ROWS  50000
#define K_CODES 1024
#define D_DIM   256
#define NTILES_N 391                 // ceil(50000/128)
#define QN ((size_t)Q_ROWS * N_ROWS)

// ---------------- argmin GEMM tiling ----------------
#define TILE_M   128
#define TILE_K   128
#define DCHUNK   32
#define NDCHUNK  (D_DIM / DCHUNK)    // 8
#define ROWSTRIDE 36
#define STAGE_F  (2 * TILE_M * ROWSTRIDE)     // 9216 floats per stage (A+B)
#define GEMM_SMEM_F (2 * STAGE_F + K_CODES)
#define GEMM_SMEM_B (GEMM_SMEM_F * 4)         // 77824 B

// ---------------- fused S+gather tiling ----------------
#define FQ 16                          // q rows per block
#define FS_AQ_F   (FQ * D_DIM)         // 4096 floats (16 KB)
#define FS_BROW   20                   // padded floats per Bbuf code row
#define FS_BBUF_F (K_CODES * FS_BROW)  // 20480 floats (80 KB)
#define FS_SMEM_F (FS_AQ_F + FS_BBUF_F)
#define FS_SMEM_B (FS_SMEM_F * 4)      // 98304 B (S[16x1024]=64KB overlays Bbuf)

// ---------------- small helpers ----------------
__device__ __forceinline__ uint32_t smem_u32(const void* p) {
    uint32_t a;
    asm("{ .reg .u64 t; cvta.to.shared.u64 t, %1; cvt.u32.u64 %0, t; }" : "=r"(a) : "l"(p));
    return a;
}
__device__ __forceinline__ void cpa16(uint32_t dst, const void* src, int szbytes) {
    asm volatile("cp.async.cg.shared.global [%0], [%1], 16, %2;\n"
                 :: "r"(dst), "l"(src), "r"(szbytes));
}
__device__ __forceinline__ void cpa_commit() { asm volatile("cp.async.commit_group;\n"); }
__device__ __forceinline__ void cpa_wait0()  { asm volatile("cp.async.wait_group 0;\n"); }

// ---------------- kernel 1: row squared-norms ----------------
__global__ void __launch_bounds__(256)
rownorm_kernel(const float* __restrict__ A, int rows, float* __restrict__ outp) {
    int row = blockIdx.x * 8 + (threadIdx.x >> 5);
    int lane = threadIdx.x & 31;
    if (row >= rows) return;
    const float4* p = (const float4*)(A + (size_t)row * D_DIM);
    float s = 0.f;
#pragma unroll
    for (int i = 0; i < 2; i++) {
        float4 v = p[lane + 32 * i];
        s += v.x * v.x + v.y * v.y + v.z * v.z + v.w * v.w;
    }
#pragma unroll
    for (int o = 16; o; o >>= 1) s += __shfl_xor_sync(0xFFFFFFFFu, s, o);
    if (lane == 0) outp[row] = s;
}

// ---------------- kernel 2: fused NN-search (argmin over codes) + vq partials ----------------
__device__ __forceinline__ void load_tiles(const float* __restrict__ A, const float* __restrict__ B,
                                           int rowbase, int rowsTotal, int cb, int d0,
                                           uint32_t smA, uint32_t smB, int tid) {
#pragma unroll
    for (int it = 0; it < 4; it++) {
        int idx = tid + 256 * it;
        int row = idx >> 3, g = idx & 7;
        int ar = rowbase + row;
        int ok = (ar < rowsTotal);
        const float* src = A + (size_t)(ok ? ar : 0) * D_DIM + d0 + 4 * g;
        cpa16(smA + (row * ROWSTRIDE + 4 * g) * 4, src, ok ? 16 : 0);
    }
#pragma unroll
    for (int it = 0; it < 4; it++) {
        int idx = tid + 256 * it;
        int row = idx >> 3, g = idx & 7;
        const float* src = B + (size_t)(cb * TILE_K + row) * D_DIM + d0 + 4 * g;
        cpa16(smB + (row * ROWSTRIDE + 4 * g) * 4, src, 16);
    }
}

__global__ void __launch_bounds__(256)
argmin_kernel(const float* __restrict__ X, const float* __restrict__ C,
              const float* __restrict__ c2p, const float* __restrict__ x2p,
              float* __restrict__ partp, float* __restrict__ idxFp) {
    extern __shared__ float sm[];
    int tid = threadIdx.x;
    int tx = tid & 15, ty = tid >> 4;
    int rowbase = blockIdx.x * TILE_M;

    float* c2s = sm + 2 * STAGE_F;
    for (int i = tid; i < K_CODES; i += 256) c2s[i] = c2p[i];

    uint32_t smA0 = smem_u32(sm);
    uint32_t smB0 = smem_u32(sm + TILE_M * ROWSTRIDE);
    uint32_t smA1 = smem_u32(sm + STAGE_F);
    uint32_t smB1 = smem_u32(sm + STAGE_F + TILE_M * ROWSTRIDE);

    float bestv[8];
    int   besti[8];
#pragma unroll
    for (int i = 0; i < 8; i++) { bestv[i] = 3.0e38f; besti[i] = 0; }

    for (int kb = 0; kb < K_CODES / TILE_K; kb++) {
        __syncthreads();     // prior stage fully consumed

        float acc[8][8];
#pragma unroll
        for (int i = 0; i < 8; i++)
#pragma unroll
            for (int j = 0; j < 8; j++) acc[i][j] = 0.f;

        load_tiles(X, C, rowbase, N_ROWS, kb, 0, smA0, smB0, tid);
        cpa_commit();

        for (int t = 0; t < NDCHUNK; t++) {
            cpa_wait0();
            __syncthreads();
            if (t + 1 < NDCHUNK) {
                uint32_t dA = ((t + 1) & 1) ? smA1 : smA0;
                uint32_t dB = ((t + 1) & 1) ? smB1 : smB0;
                load_tiles(X, C, rowbase, N_ROWS, kb, (t + 1) * DCHUNK, dA, dB, tid);
                cpa_commit();
            }
            const float* As = sm + (t & 1) * STAGE_F;
            const float* Bs = As + TILE_M * ROWSTRIDE;
#pragma unroll 4
            for (int kk = 0; kk < DCHUNK; kk++) {
                float a[8], b[8];
#pragma unroll
                for (int i = 0; i < 8; i++) a[i] = As[(ty * 8 + i) * ROWSTRIDE + kk];
#pragma unroll
                for (int j = 0; j < 8; j++) b[j] = Bs[(tx + 16 * j) * ROWSTRIDE + kk];
#pragma unroll
                for (int i = 0; i < 8; i++)
#pragma unroll
                    for (int j = 0; j < 8; j++)
                        acc[i][j] = fmaf(a[i], b[j], acc[i][j]);
            }
            __syncthreads();
        }

#pragma unroll
        for (int i = 0; i < 8; i++) {
#pragma unroll
            for (int j = 0; j < 8; j++) {
                int c = kb * TILE_K + tx + 16 * j;
                float v = c2s[c] - 2.0f * acc[i][j];
                if (v < bestv[i] || (v == bestv[i] && c < besti[i])) { bestv[i] = v; besti[i] = c; }
            }
        }
    }

    // cross-tx reduce via smem (reuse tile buffers)
    __syncthreads();
    float* red_v = sm;                       // [128][16]
    int*   red_i = (int*)(sm + 2048);        // [128][16]
    float* rowd  = sm + 4096;                // [128]
#pragma unroll
    for (int i = 0; i < 8; i++) {
        int r = ty * 8 + i;
        red_v[r * 16 + tx] = bestv[i];
        red_i[r * 16 + tx] = besti[i];
    }
    __syncthreads();
    if (tid < 128) {
        int r = tid;
        float bv = red_v[r * 16]; int bi = red_i[r * 16];
#pragma unroll
        for (int t = 1; t < 16; t++) {
            float v = red_v[r * 16 + t]; int ii = red_i[r * 16 + t];
            if (v < bv || (v == bv && ii < bi)) { bv = v; bi = ii; }
        }
        int rowg = rowbase + r;
        float d2 = 0.f;
        if (rowg < N_ROWS) {
            d2 = x2p[rowg] + bv;
            idxFp[rowg] = (float)bi;
        }
        rowd[r] = d2;
    }
    __syncthreads();
    for (int s = 64; s >= 1; s >>= 1) {
        if (tid < s && tid + s < 128) rowd[tid] += rowd[tid + s];
        __syncthreads();
    }
    if (tid == 0) partp[blockIdx.x] = rowd[0];
}

// ---------------- kernel 3: vq_loss finalize ----------------
__global__ void __launch_bounds__(256)
finalize_kernel(const float* __restrict__ partp, float* __restrict__ lossp, int writeLoss) {
    __shared__ float s[256];
    int tid = threadIdx.x;
    float v = 0.f;
    for (int i = tid; i < NTILES_N; i += 256) v += partp[i];
    s[tid] = v;
    __syncthreads();
    for (int o = 128; o >= 1; o >>= 1) {
        if (tid < o) s[tid] += s[tid + o];
        __syncthreads();
    }
    if (tid == 0 && writeLoss) {
        lossp[0] = 1.25f * s[0] / ((float)N_ROWS * (float)D_DIM);
    }
}

// ---------------- kernel 4: fused S-compute + gather ----------------
// Block b owns q-rows [16b, 16b+16). Computes S[16][1024] = Qrows @ C^T in smem,
// then writes score[q][n] = S[q - qb][idx[n]] for all n.
__global__ void __launch_bounds__(256)
fused_score_kernel(const float* __restrict__ Qm, const float* __restrict__ Cm,
                   const float* __restrict__ idxFp, float* __restrict__ outp) {
    extern __shared__ float sm[];
    int tid = threadIdx.x;
    int qb = blockIdx.x * FQ;

    // ---- load 16 query rows into smem (Aq[16][256]) ----
#pragma unroll
    for (int it = 0; it < 4; it++) {
        int id = tid + 256 * it;       // 0..1023
        int row = id >> 6;
        int c4 = id & 63;
        *(float4*)(sm + row * D_DIM + c4 * 4) =
            *(const float4*)(Qm + (size_t)(qb + row) * D_DIM + c4 * 4);
    }

    int qg = tid >> 7;     // 0..1  (8-row group)
    int cg = tid & 127;    // 0..127 (8-code group)
    int sw = cg & 3;       // bank swizzle key

    float acc[8][8];
#pragma unroll
    for (int i = 0; i < 8; i++)
#pragma unroll
        for (int j = 0; j < 8; j++) acc[i][j] = 0.f;

    uint32_t bbase = smem_u32(sm + FS_AQ_F);

    for (int dc = 0; dc < D_DIM / 16; dc++) {   // 16 chunks of 16 d
        __syncthreads();   // prior chunk consumed (and Aq ready on first iter)
        // stage codebook chunk: Bbuf[1024 codes][16 d] (padded row = 20 floats, xor-swizzled)
#pragma unroll
        for (int it = 0; it < 16; it++) {
            int id = tid + 256 * it;   // 0..4095
            int code = id >> 2;
            int dg = id & 3;
            int dsw = dg ^ ((code >> 3) & 3);
            cpa16(bbase + (uint32_t)(code * FS_BROW + dsw * 4) * 4,
                  Cm + (size_t)code * D_DIM + dc * 16 + dg * 4, 16);
        }
        cpa_commit();
        cpa_wait0();
        __syncthreads();

        const float* Bb = sm + FS_AQ_F;
#pragma unroll
        for (int kk4 = 0; kk4 < 4; kk4++) {
            int ks = (kk4 ^ sw) << 2;
            float4 b4[8];
#pragma unroll
            for (int j = 0; j < 8; j++)
                b4[j] = *(const float4*)(Bb + (cg * 8 + j) * FS_BROW + ks);
#pragma unroll
            for (int i = 0; i < 8; i++) {
                float4 a4 = *(const float4*)(sm + (qg * 8 + i) * D_DIM + dc * 16 + kk4 * 4);
#pragma unroll
                for (int j = 0; j < 8; j++) {
                    acc[i][j] = fmaf(a4.x, b4[j].x, acc[i][j]);
                    acc[i][j] = fmaf(a4.y, b4[j].y, acc[i][j]);
                    acc[i][j] = fmaf(a4.z, b4[j].z, acc[i][j]);
                    acc[i][j] = fmaf(a4.w, b4[j].w, acc[i][j]);
                }
            }
        }
    }

    __syncthreads();   // all Bbuf reads done before S overlays it
    float* S = sm + FS_AQ_F;     // S[16][1024] overlays Bbuf
#pragma unroll
    for (int i = 0; i < 8; i++) {
#pragma unroll
        for (int j4 = 0; j4 < 2; j4++) {
            float4 v = make_float4(acc[i][j4 * 4 + 0], acc[i][j4 * 4 + 1],
                                   acc[i][j4 * 4 + 2], acc[i][j4 * 4 + 3]);
            *(float4*)(S + (qg * 8 + i) * K_CODES + cg * 8 + j4 * 4) = v;
        }
    }
    __syncthreads();

    // ---- gather phase: score[qb+q][n] = S[q][idx[n]] ----
    for (int base = 0; base < N_ROWS; base += 1024) {
        int n = base + (tid << 2);
        if (n < N_ROWS) {          // N_ROWS % 4 == 0 -> whole float4 valid
            int i0 = (int)(idxFp[n + 0] + 0.5f);
            int i1 = (int)(idxFp[n + 1] + 0.5f);
            int i2 = (int)(idxFp[n + 2] + 0.5f);
            int i3 = (int)(idxFp[n + 3] + 0.5f);
#pragma unroll
            for (int q = 0; q < FQ; q++) {
                const float* Sr = S + q * K_CODES;
                float4 v = make_float4(Sr[i0], Sr[i1], Sr[i2], Sr[i3]);
                *(float4*)(outp + (size_t)(qb + q) * N_ROWS + n) = v;
            }
        }
    }
}

// ---------------- host launch ----------------
extern "C" void kernel_launch(void* const* d_in, const int* in_sizes, int n_in,
                              void* d_out, int out_size) {
    const float* Qm = nullptr;
    const float* Xm = nullptr;
    const float* Cm = nullptr;
    for (int i = 0; i < n_in; i++) {
        if (in_sizes[i] == Q_ROWS * D_DIM)       Qm = (const float*)d_in[i];
        else if (in_sizes[i] == N_ROWS * D_DIM)  Xm = (const float*)d_in[i];
        else if (in_sizes[i] == K_CODES * D_DIM) Cm = (const float*)d_in[i];
    }
    if (!Qm && n_in > 0) Qm = (const float*)d_in[0];
    if (!Xm && n_in > 1) Xm = (const float*)d_in[1];
    if (!Cm && n_in > 2) Cm = (const float*)d_in[2];

    float* out = (float*)d_out;
    bool hasExtra = ((size_t)out_size >= QN + 1 + N_ROWS);

    // Scratch carved out of the score region (overwritten last by fused_score):
    float* c2p   = out;            // [0, 1024)
    float* partp = out + 1024;     // [1024, 1415)
    float* x2p   = out + 2048;     // [2048, 52048)
    float* idxp  = hasExtra ? (out + QN + 1) : (out + (QN - N_ROWS));
    float* lossp = out + QN;       // only written when hasExtra

    (void)cudaFuncSetAttribute(argmin_kernel,      cudaFuncAttributeMaxDynamicSharedMemorySize, GEMM_SMEM_B);
    (void)cudaFuncSetAttribute(fused_score_kernel, cudaFuncAttributeMaxDynamicSharedMemorySize, FS_SMEM_B);

    // 1. norms (stream-ordered producers of c2/x2 scratch)
    rownorm_kernel<<<(K_CODES + 7) / 8, 256>>>(Cm, K_CODES, c2p);
    rownorm_kernel<<<(N_ROWS + 7) / 8, 256>>>(Xm, N_ROWS, x2p);

    // 2. nearest-neighbor argmin + vq partials (writes idx to its output slot)
    argmin_kernel<<<NTILES_N, 256, GEMM_SMEM_B>>>(Xm, Cm, c2p, x2p, partp, idxp);

    // 3. vq_loss
    finalize_kernel<<<1, 256>>>(partp, lossp, hasExtra ? 1 : 0);

    // 4. fused S = Q@C^T (per-block, in smem) + score gather (overwrites all scratch)
    fused_score_kernel<<<Q_ROWS / FQ, 256, FS_SMEM_B>>>(Qm, Cm, idxp, out);
}